// round 15
// baseline (speedup 1.0000x reference)
#include <cuda_runtime.h>
#include <cstdint>
#include <math.h>

#define BDIM 2
#define TDIM 2048
#define CDIM 1024
#define NH 16
#define HD 64
#define MDIM (BDIM*TDIM)   // 4096
#define NQKV (3*CDIM)      // 3072

// Scratch (allocation-free rule: __device__ globals)
__device__ float g_q[BDIM*NH*TDIM*HD];    // pre-scaled by 0.125
__device__ float g_k[BDIM*NH*TDIM*HD];
__device__ float g_vt[BDIM*NH*HD*TDIM];   // V transposed: [bh][d][t]
__device__ float g_y[MDIM*CDIM];          // tf32-rounded by flash epilogue
__device__ float g_x32[MDIM*CDIM];        // x, tf32-rounded
__device__ float g_wt_qkv[NQKV*CDIM];     // W_qkv^T [N][K], tf32-rounded
__device__ float g_wt_proj[CDIM*CDIM];    // W_proj^T [N][K], tf32-rounded

__device__ __forceinline__ uint32_t cvt_tf32(float x) {
    uint32_t r; asm("cvt.rna.tf32.f32 %0, %1;" : "=r"(r) : "f"(x)); return r;
}
__device__ __forceinline__ void mma_tf32(float* d, const uint32_t* a, const uint32_t* b) {
    asm volatile(
        "mma.sync.aligned.m16n8k8.row.col.f32.tf32.tf32.f32 "
        "{%0,%1,%2,%3}, {%4,%5,%6,%7}, {%8,%9}, {%0,%1,%2,%3};"
        : "+f"(d[0]), "+f"(d[1]), "+f"(d[2]), "+f"(d[3])
        : "r"(a[0]), "r"(a[1]), "r"(a[2]), "r"(a[3]), "r"(b[0]), "r"(b[1]));
}
__device__ __forceinline__ void cp16(uint32_t daddr, const void* g) {
    asm volatile("cp.async.cg.shared.global [%0], [%1], 16;" :: "r"(daddr), "l"(g) : "memory");
}
__device__ __forceinline__ void ldsm4(uint32_t* r, uint32_t saddr) {
    asm volatile("ldmatrix.sync.aligned.m8n8.x4.shared.b16 {%0,%1,%2,%3}, [%4];"
        : "=r"(r[0]), "=r"(r[1]), "=r"(r[2]), "=r"(r[3]) : "r"(saddr));
}

// ================= pre-round x to tf32 =================
__global__ __launch_bounds__(256) void cvt_x32_kernel(const float* __restrict__ x)
{
    int i = blockIdx.x * 256 + threadIdx.x;
    float4 v = ((const float4*)x)[i];
    ((uint4*)g_x32)[i] = make_uint4(cvt_tf32(v.x), cvt_tf32(v.y), cvt_tf32(v.z), cvt_tf32(v.w));
}

// ================= transpose + tf32 convert =================
__global__ __launch_bounds__(256) void transpose_cvt(
    const float* __restrict__ W, float* __restrict__ WT, int N)
{
    __shared__ float t[32][33];
    int n0 = blockIdx.x * 32, k0 = blockIdx.y * 32;
    int tx = threadIdx.x & 31, ty = threadIdx.x >> 5;
    #pragma unroll
    for (int i = 0; i < 4; i++)
        t[ty + i * 8][tx] = W[(size_t)(k0 + ty + i * 8) * N + n0 + tx];
    __syncthreads();
    #pragma unroll
    for (int i = 0; i < 4; i++)
        WT[(size_t)(n0 + ty + i * 8) * CDIM + k0 + tx] =
            __uint_as_float(cvt_tf32(t[tx][ty + i * 8]));
}

// ================= tf32 mma.sync GEMM: BK=32, 2-stage cp.async, 3 CTAs/SM =================
// BM=BN=128, 8 warps (2x4), warp tile 64x32. smem [row][36] pad (banks 4r+c, conflict-free).
// Schedule per iter: wait_group 0 -> __syncthreads -> issue(it+1) -> compute(it).
// wait BEFORE barrier (cp.async completion is per-thread; the barrier publishes it).
#define GPITCH (128*36)
#define GSMEM (4*GPITCH*4)     // 2 stages x (A+B) = 73728 B -> 3 CTAs/SM

__device__ __forceinline__ void gemm_issue(
    uint32_t* As, uint32_t* Bs, const float* Ap, const float* Bp,
    int stage, int k0, int lr2, int lc4)
{
    #pragma unroll
    for (int i = 0; i < 4; i++) {
        const int r = lr2 + i * 32;
        cp16((uint32_t)__cvta_generic_to_shared(As + stage * GPITCH + r * 36 + lc4),
             Ap + (size_t)r * CDIM + k0 + lc4);
        cp16((uint32_t)__cvta_generic_to_shared(Bs + stage * GPITCH + r * 36 + lc4),
             Bp + (size_t)r * CDIM + k0 + lc4);
    }
    asm volatile("cp.async.commit_group;" ::: "memory");
}

__device__ __forceinline__ void mma_mainloop(
    const float* __restrict__ Ap, const float* __restrict__ Bp,
    float (&acc)[4][4][4], int tid, uint32_t* smem)
{
    uint32_t* As = smem;               // [2][128][36]
    uint32_t* Bs = smem + 2 * GPITCH;
    const uint32_t As_s = (uint32_t)__cvta_generic_to_shared(As);
    const uint32_t Bs_s = (uint32_t)__cvta_generic_to_shared(Bs);
    const int lane = tid & 31, wid = tid >> 5;
    const int wm = wid >> 2, wn = wid & 3;
    const int lr2 = tid >> 3, lc4 = (tid & 7) * 4;     // 32 rows x 8 float4 per pass
    const int lq = lane & 7, j = lane >> 3;

    uint32_t a_off[4], b_off[2];
    #pragma unroll
    for (int mt = 0; mt < 4; mt++)
        a_off[mt] = ((wm * 64 + mt * 16 + (j & 1) * 8 + lq) * 36 + (j >> 1) * 4) * 4;
    #pragma unroll
    for (int p = 0; p < 2; p++)
        b_off[p] = ((wn * 32 + (2 * p + (j >> 1)) * 8 + lq) * 36 + (j & 1) * 4) * 4;

    #pragma unroll
    for (int mt = 0; mt < 4; mt++)
        #pragma unroll
        for (int nt = 0; nt < 4; nt++)
            #pragma unroll
            for (int jj = 0; jj < 4; jj++) acc[mt][nt][jj] = 0.f;

    gemm_issue(As, Bs, Ap, Bp, 0, 0, lr2, lc4);

    for (int it = 0; it < 32; it++) {
        // 1) my group for stage it&1 has landed
        asm volatile("cp.async.wait_group 0;" ::: "memory");
        // 2) publish: ALL threads' groups landed; ALL warps done compute(it-1)
        //    (which read stage (it+1)&1 — so it is now safe to overwrite)
        __syncthreads();
        // 3) prefetch next stage; overlaps with compute(it)
        if (it + 1 < 32)
            gemm_issue(As, Bs, Ap, Bp, (it + 1) & 1, (it + 1) * 32, lr2, lc4);

        const int cur = it & 1;
        const uint32_t Ab = As_s + cur * (GPITCH * 4);
        const uint32_t Bb = Bs_s + cur * (GPITCH * 4);
        #pragma unroll
        for (int ks = 0; ks < 4; ks++) {
            uint32_t af[4][4];
            #pragma unroll
            for (int mt = 0; mt < 4; mt++) ldsm4(af[mt], Ab + a_off[mt] + ks * 32);
            uint32_t bf[8];
            #pragma unroll
            for (int p = 0; p < 2; p++) ldsm4(bf + 4 * p, Bb + b_off[p] + ks * 32);
            #pragma unroll
            for (int mt = 0; mt < 4; mt++)
                #pragma unroll
                for (int nt = 0; nt < 4; nt++)
                    mma_tf32(acc[mt][nt], af[mt], &bf[2 * nt]);
        }
    }
}

__global__ __launch_bounds__(256, 3) void gemm_qkv_mma(
    const float* __restrict__ sinp, const float* __restrict__ cosp)
{
    extern __shared__ uint32_t smu[];
    const int tid = threadIdx.x;
    const int m0 = blockIdx.y * 128, n0 = blockIdx.x * 128;
    float acc[4][4][4];
    mma_mainloop(g_x32 + (size_t)m0 * CDIM, g_wt_qkv + (size_t)n0 * CDIM, acc, tid, smu);

    const int lane = tid & 31, wid = tid >> 5;
    const int wm = wid >> 2, wn = wid & 3;
    const int sec = n0 >> 10;
    const int nb = n0 & 1023;

    #pragma unroll
    for (int mt = 0; mt < 4; mt++) {
        #pragma unroll
        for (int nt = 0; nt < 4; nt++) {
            const int col = wn * 32 + nt * 8 + (lane & 3) * 2;
            const int nc = nb + col;
            const int h = nc >> 6, d = nc & 63;
            #pragma unroll
            for (int half = 0; half < 2; half++) {
                const int row = m0 + wm * 64 + mt * 16 + (lane >> 2) + half * 8;
                const int b = row >> 11, t = row & 2047;
                const int bh = b * NH + h;
                float v0 = acc[mt][nt][half * 2], v1 = acc[mt][nt][half * 2 + 1];
                if (sec < 2) {
                    float ca = cosp[t * HD + d], sa = sinp[t * HD + d];
                    float o0 = v0 * ca - v1 * sa;
                    float o1 = v1 * ca + v0 * sa;
                    if (sec == 0) { o0 *= 0.125f; o1 *= 0.125f; }   // fold softmax scale (exact)
                    float* dst = (sec == 0) ? g_q : g_k;
                    *(float2*)(dst + (((size_t)bh * TDIM + t) * HD + d)) =
                        make_float2(__uint_as_float(cvt_tf32(o0)), __uint_as_float(cvt_tf32(o1)));
                } else {
                    g_vt[((size_t)bh * HD + d) * TDIM + t]     = __uint_as_float(cvt_tf32(v0));
                    g_vt[((size_t)bh * HD + d + 1) * TDIM + t] = __uint_as_float(cvt_tf32(v1));
                }
            }
        }
    }
}

__global__ __launch_bounds__(256, 3) void gemm_proj_mma(float* __restrict__ out)
{
    extern __shared__ uint32_t smu[];
    const int tid = threadIdx.x;
    const int m0 = blockIdx.y * 128, n0 = blockIdx.x * 128;
    float acc[4][4][4];
    mma_mainloop(g_y + (size_t)m0 * CDIM, g_wt_proj + (size_t)n0 * CDIM, acc, tid, smu);

    const int lane = tid & 31, wid = tid >> 5;
    const int wm = wid >> 2, wn = wid & 3;
    #pragma unroll
    for (int mt = 0; mt < 4; mt++) {
        #pragma unroll
        for (int nt = 0; nt < 4; nt++) {
            const int col = n0 + wn * 32 + nt * 8 + (lane & 3) * 2;
            #pragma unroll
            for (int half = 0; half < 2; half++) {
                const int row = m0 + wm * 64 + mt * 16 + (lane >> 2) + half * 8;
                *(float2*)(out + (size_t)row * CDIM + col) =
                    make_float2(acc[mt][nt][half * 2], acc[mt][nt][half * 2 + 1]);
            }
        }
    }
}

// ================= flash attention: mma.sync tf32, full-ldmatrix =================
// CTA: 64 q-rows, 4 warps (warp = 16 q x 64 k). BK=64, cp.async double buffer.
// Q is pre-scaled by 0.125 (folded softmax scale).
#define FA_SMEM 104448

__global__ __launch_bounds__(128) void flash_mma()
{
    extern __shared__ float sm[];
    float* Qs = sm;                 // [64][68]
    float* Ps = sm + 4352;          // [64][68]
    float* KsB = sm + 8704;         // [2][64][68]
    float* VsB = sm + 17408;        // [2][64][68]  (Vt: rows=d, cols=t)

    const int bh = blockIdx.x;
    const int qt = 31 - blockIdx.y;         // long CTAs first
    const int q0 = qt * 64;
    const int tid = threadIdx.x;
    const int lane = tid & 31, wid = tid >> 5;
    const int fr = lane >> 2, fc = lane & 3;
    const int lq = lane & 7, j = lane >> 3;
    const int wq = wid * 16;

    const float* qb = g_q + (size_t)bh * TDIM * HD;
    const float* kb = g_k + (size_t)bh * TDIM * HD;
    const float* vtb = g_vt + (size_t)bh * HD * TDIM;

    const uint32_t Qs_s = (uint32_t)__cvta_generic_to_shared(Qs);
    const uint32_t Ps_s = (uint32_t)__cvta_generic_to_shared(Ps);
    const uint32_t Ks_s = (uint32_t)__cvta_generic_to_shared(KsB);
    const uint32_t Vs_s = (uint32_t)__cvta_generic_to_shared(VsB);

    const uint32_t q_off = ((wq + (j & 1) * 8 + lq) * 68 + (j >> 1) * 4) * 4;
    uint32_t b_off[4];
    #pragma unroll
    for (int p = 0; p < 4; p++)
        b_off[p] = (((2 * p + (j >> 1)) * 8 + lq) * 68 + (j & 1) * 4) * 4;

    #pragma unroll
    for (int i = 0; i < 8; i++) {
        int lin = tid + i * 128;
        int r = lin >> 4, c4 = (lin & 15) * 4;
        *(float4*)(Qs + r * 68 + c4) = *(const float4*)(qb + (size_t)(q0 + r) * HD + c4);
    }
    #pragma unroll
    for (int i = 0; i < 8; i++) {
        int lin = tid + i * 128;
        int r = lin >> 4, c4 = (lin & 15) * 4;
        cp16((uint32_t)__cvta_generic_to_shared(KsB + r * 68 + c4),
             kb + (size_t)r * HD + c4);
        cp16((uint32_t)__cvta_generic_to_shared(VsB + r * 68 + c4),
             vtb + (size_t)r * TDIM + c4);
    }
    asm volatile("cp.async.commit_group;" ::: "memory");

    float o[8][4];
    #pragma unroll
    for (int nt = 0; nt < 8; nt++)
        #pragma unroll
        for (int jj = 0; jj < 4; jj++) o[nt][jj] = 0.f;
    float m0 = -1e30f, m1 = -1e30f, l0 = 0.f, l1 = 0.f;

    for (int kt = 0; kt <= qt; kt++) {
        const int buf = kt & 1;
        if (kt < qt) {
            const int kr = (kt + 1) * 64;
            float* Kn = KsB + (buf ^ 1) * 4352;
            float* Vn = VsB + (buf ^ 1) * 4352;
            #pragma unroll
            for (int i = 0; i < 8; i++) {
                int lin = tid + i * 128;
                int r = lin >> 4, c4 = (lin & 15) * 4;
                cp16((uint32_t)__cvta_generic_to_shared(Kn + r * 68 + c4),
                     kb + (size_t)(kr + r) * HD + c4);
                cp16((uint32_t)__cvta_generic_to_shared(Vn + r * 68 + c4),
                     vtb + (size_t)r * TDIM + kr + c4);
            }
            asm volatile("cp.async.commit_group;" ::: "memory");
            asm volatile("cp.async.wait_group 1;" ::: "memory");
        } else {
            asm volatile("cp.async.wait_group 0;" ::: "memory");
        }
        __syncthreads();

        const uint32_t Kb_s = Ks_s + buf * (4352 * 4);
        const uint32_t Vb_s = Vs_s + buf * (4352 * 4);

        // ---- S = Q K^T  (scale pre-folded into Q) ----
        float s[8][4];
        #pragma unroll
        for (int nt = 0; nt < 8; nt++)
            #pragma unroll
            for (int jj = 0; jj < 4; jj++) s[nt][jj] = 0.f;
        #pragma unroll
        for (int ks = 0; ks < 8; ks++) {
            uint32_t a[4];
            ldsm4(a, Qs_s + q_off + ks * 32);
            uint32_t kf[16];
            #pragma unroll
            for (int p = 0; p < 4; p++) ldsm4(kf + 4 * p, Kb_s + b_off[p] + ks * 32);
            #pragma unroll
            for (int nt = 0; nt < 8; nt++)
                mma_tf32(s[nt], a, &kf[2 * nt]);
        }

        if (kt == qt) {
            const int r0 = wq + fr, r1 = r0 + 8;
            #pragma unroll
            for (int nt = 0; nt < 8; nt++) {
                const int cl = nt * 8 + 2 * fc;
                if (cl > r0)     s[nt][0] = -1e30f;
                if (cl + 1 > r0) s[nt][1] = -1e30f;
                if (cl > r1)     s[nt][2] = -1e30f;
                if (cl + 1 > r1) s[nt][3] = -1e30f;
            }
        }

        // ---- online softmax (warp-local quad shuffles) ----
        float mx0 = -1e30f, mx1 = -1e30f;
        #pragma unroll
        for (int nt = 0; nt < 8; nt++) {
            mx0 = fmaxf(mx0, fmaxf(s[nt][0], s[nt][1]));
            mx1 = fmaxf(mx1, fmaxf(s[nt][2], s[nt][3]));
        }
        mx0 = fmaxf(mx0, __shfl_xor_sync(0xffffffffu, mx0, 1));
        mx0 = fmaxf(mx0, __shfl_xor_sync(0xffffffffu, mx0, 2));
        mx1 = fmaxf(mx1, __shfl_xor_sync(0xffffffffu, mx1, 1));
        mx1 = fmaxf(mx1, __shfl_xor_sync(0xffffffffu, mx1, 2));
        const float mn0 = fmaxf(m0, mx0), mn1 = fmaxf(m1, mx1);
        const float al0 = __expf(m0 - mn0), al1 = __expf(m1 - mn1);
        m0 = mn0; m1 = mn1;

        float ps0 = 0.f, ps1 = 0.f;
        #pragma unroll
        for (int nt = 0; nt < 8; nt++) {
            float p0 = __expf(s[nt][0] - mn0);
            float p1 = __expf(s[nt][1] - mn0);
            float p2 = __expf(s[nt][2] - mn1);
            float p3 = __expf(s[nt][3] - mn1);
            ps0 += p0 + p1; ps1 += p2 + p3;
            const int cl = nt * 8 + 2 * fc;
            Ps[(wq + fr) * 68 + cl]     = p0;
            Ps[(wq + fr) * 68 + cl + 1] = p1;
            Ps[(wq + fr + 8) * 68 + cl]     = p2;
            Ps[(wq + fr + 8) * 68 + cl + 1] = p3;
        }
        ps0 += __shfl_xor_sync(0xffffffffu, ps0, 1);
        ps0 += __shfl_xor_sync(0xffffffffu, ps0, 2);
        ps1 += __shfl_xor_sync(0xffffffffu, ps1, 1);
        ps1 += __shfl_xor_sync(0xffffffffu, ps1, 2);
        l0 = l0 * al0 + ps0;
        l1 = l1 * al1 + ps1;
        #pragma unroll
        for (int nt = 0; nt < 8; nt++) {
            o[nt][0] *= al0; o[nt][1] *= al0;
            o[nt][2] *= al1; o[nt][3] *= al1;
        }
        __syncwarp();

        // ---- O += P V  (ldmatrix on Vt) ----
        #pragma unroll
        for (int ks = 0; ks < 8; ks++) {
            uint32_t a[4];
            ldsm4(a, Ps_s + q_off + ks * 32);
            uint32_t vf[16];
            #pragma unroll
            for (int p = 0; p < 4; p++) ldsm4(vf + 4 * p, Vb_s + b_off[p] + ks * 32);
            #pragma unroll
            for (int nt = 0; nt < 8; nt++)
                mma_tf32(o[nt], a, &vf[2 * nt]);
        }
        __syncthreads();
    }

    // ---- epilogue: O/l -> g_y [B,T,C], tf32-rounded ----
    const float inv0 = 1.0f / l0, inv1 = 1.0f / l1;
    const int b = bh >> 4, h = bh & 15;
    const int t0 = q0 + wq + fr, t1 = t0 + 8;
    #pragma unroll
    for (int nt = 0; nt < 8; nt++) {
        const int d = nt * 8 + 2 * fc;
        *(float2*)(g_y + (size_t)(b * TDIM + t0) * CDIM + h * HD + d) =
            make_float2(__uint_as_float(cvt_tf32(o[nt][0] * inv0)),
                        __uint_as_float(cvt_tf32(o[nt][1] * inv0)));
        *(float2*)(g_y + (size_t)(b * TDIM + t1) * CDIM + h * HD + d) =
            make_float2(__uint_as_float(cvt_tf32(o[nt][2] * inv1)),
                        __uint_as_float(cvt_tf32(o[nt][3] * inv1)));
    }
}

// ================= launch =================
extern "C" void kernel_launch(void* const* d_in, const int* in_sizes, int n_in,
                              void* d_out, int out_size)
{
    const float* x     = (const float*)d_in[0];
    const float* sinp  = (const float*)d_in[1];
    const float* cosp  = (const float*)d_in[2];
    const float* Wqkv  = (const float*)d_in[3];
    const float* Wproj = (const float*)d_in[4];
    float* out = (float*)d_out;

    float* wt_qkv;  cudaGetSymbolAddress((void**)&wt_qkv,  g_wt_qkv);
    float* wt_proj; cudaGetSymbolAddress((void**)&wt_proj, g_wt_proj);

    cudaFuncSetAttribute(flash_mma,     cudaFuncAttributeMaxDynamicSharedMemorySize, FA_SMEM);
    cudaFuncSetAttribute(gemm_qkv_mma,  cudaFuncAttributeMaxDynamicSharedMemorySize, GSMEM);
    cudaFuncSetAttribute(gemm_proj_mma, cudaFuncAttributeMaxDynamicSharedMemorySize, GSMEM);

    cvt_x32_kernel<<<MDIM * CDIM / 4 / 256, 256>>>(x);
    transpose_cvt<<<dim3(NQKV / 32, CDIM / 32), 256>>>(Wqkv,  wt_qkv,  NQKV);
    transpose_cvt<<<dim3(CDIM / 32, CDIM / 32), 256>>>(Wproj, wt_proj, CDIM);

    gemm_qkv_mma<<<dim3(NQKV / 128, MDIM / 128), 256, GSMEM>>>(sinp, cosp);
    flash_mma<<<dim3(BDIM * NH, TDIM / 64), 128, FA_SMEM>>>();
    gemm_proj_mma<<<dim3(CDIM / 128, MDIM / 128), 256, GSMEM>>>(out);
}

// round 16
// speedup vs baseline: 1.5771x; 1.5771x over previous
#include <cuda_runtime.h>
#include <cstdint>
#include <math.h>

#define BDIM 2
#define TDIM 2048
#define CDIM 1024
#define NH 16
#define HD 64
#define MDIM (BDIM*TDIM)   // 4096
#define NQKV (3*CDIM)      // 3072

// Scratch (allocation-free rule: __device__ globals)
__device__ float g_q[BDIM*NH*TDIM*HD];    // pre-scaled by 0.125
__device__ float g_k[BDIM*NH*TDIM*HD];
__device__ float g_vt[BDIM*NH*HD*TDIM];   // V transposed: [bh][d][t]
__device__ float g_y[MDIM*CDIM];          // tf32-rounded by flash epilogue
__device__ float g_x32[MDIM*CDIM];        // x, tf32-rounded
__device__ float g_wt_qkv[NQKV*CDIM];     // W_qkv^T [N][K], tf32-rounded
__device__ float g_wt_proj[CDIM*CDIM];    // W_proj^T [N][K], tf32-rounded

__device__ __forceinline__ uint32_t cvt_tf32(float x) {
    uint32_t r; asm("cvt.rna.tf32.f32 %0, %1;" : "=r"(r) : "f"(x)); return r;
}
__device__ __forceinline__ void mma_tf32(float* d, const uint32_t* a, const uint32_t* b) {
    asm volatile(
        "mma.sync.aligned.m16n8k8.row.col.f32.tf32.tf32.f32 "
        "{%0,%1,%2,%3}, {%4,%5,%6,%7}, {%8,%9}, {%0,%1,%2,%3};"
        : "+f"(d[0]), "+f"(d[1]), "+f"(d[2]), "+f"(d[3])
        : "r"(a[0]), "r"(a[1]), "r"(a[2]), "r"(a[3]), "r"(b[0]), "r"(b[1]));
}
__device__ __forceinline__ void cp16(uint32_t daddr, const void* g) {
    asm volatile("cp.async.cg.shared.global [%0], [%1], 16;" :: "r"(daddr), "l"(g) : "memory");
}
__device__ __forceinline__ void ldsm4(uint32_t* r, uint32_t saddr) {
    asm volatile("ldmatrix.sync.aligned.m8n8.x4.shared.b16 {%0,%1,%2,%3}, [%4];"
        : "=r"(r[0]), "=r"(r[1]), "=r"(r[2]), "=r"(r[3]) : "r"(saddr));
}

// ================= pre-round x to tf32 =================
__global__ __launch_bounds__(256) void cvt_x32_kernel(const float* __restrict__ x)
{
    int i = blockIdx.x * 256 + threadIdx.x;
    float4 v = ((const float4*)x)[i];
    ((uint4*)g_x32)[i] = make_uint4(cvt_tf32(v.x), cvt_tf32(v.y), cvt_tf32(v.z), cvt_tf32(v.w));
}

// ================= transpose + tf32 convert =================
__global__ __launch_bounds__(256) void transpose_cvt(
    const float* __restrict__ W, float* __restrict__ WT, int N)
{
    __shared__ float t[32][33];
    int n0 = blockIdx.x * 32, k0 = blockIdx.y * 32;
    int tx = threadIdx.x & 31, ty = threadIdx.x >> 5;
    #pragma unroll
    for (int i = 0; i < 4; i++)
        t[ty + i * 8][tx] = W[(size_t)(k0 + ty + i * 8) * N + n0 + tx];
    __syncthreads();
    #pragma unroll
    for (int i = 0; i < 4; i++)
        WT[(size_t)(n0 + ty + i * 8) * CDIM + k0 + tx] =
            __uint_as_float(cvt_tf32(t[tx][ty + i * 8]));
}

// ===== tf32 mma.sync GEMM: BK=32, 3-stage cp.async + ldmatrix (R13 config, proven) =====
#define GPITCH (128*36)
#define GSMEM (6*GPITCH*4)     // 3 stages x (A+B) = 110592 B

__device__ __forceinline__ void gemm_issue(
    uint32_t* As, uint32_t* Bs, const float* Ap, const float* Bp,
    int stage, int k0, int lr2, int lc4)
{
    #pragma unroll
    for (int i = 0; i < 4; i++) {
        const int r = lr2 + i * 32;
        cp16((uint32_t)__cvta_generic_to_shared(As + stage * GPITCH + r * 36 + lc4),
             Ap + (size_t)r * CDIM + k0 + lc4);
        cp16((uint32_t)__cvta_generic_to_shared(Bs + stage * GPITCH + r * 36 + lc4),
             Bp + (size_t)r * CDIM + k0 + lc4);
    }
    asm volatile("cp.async.commit_group;" ::: "memory");
}

__device__ __forceinline__ void mma_mainloop(
    const float* __restrict__ Ap, const float* __restrict__ Bp,
    float (&acc)[4][4][4], int tid, uint32_t* smem)
{
    uint32_t* As = smem;               // [3][128][36]
    uint32_t* Bs = smem + 3 * GPITCH;
    const uint32_t As_s = (uint32_t)__cvta_generic_to_shared(As);
    const uint32_t Bs_s = (uint32_t)__cvta_generic_to_shared(Bs);
    const int lane = tid & 31, wid = tid >> 5;
    const int wm = wid >> 2, wn = wid & 3;
    const int lr2 = tid >> 3, lc4 = (tid & 7) * 4;
    const int lq = lane & 7, j = lane >> 3;

    uint32_t a_off[4], b_off[2];
    #pragma unroll
    for (int mt = 0; mt < 4; mt++)
        a_off[mt] = ((wm * 64 + mt * 16 + (j & 1) * 8 + lq) * 36 + (j >> 1) * 4) * 4;
    #pragma unroll
    for (int p = 0; p < 2; p++)
        b_off[p] = ((wn * 32 + (2 * p + (j >> 1)) * 8 + lq) * 36 + (j & 1) * 4) * 4;

    #pragma unroll
    for (int mt = 0; mt < 4; mt++)
        #pragma unroll
        for (int nt = 0; nt < 4; nt++)
            #pragma unroll
            for (int jj = 0; jj < 4; jj++) acc[mt][nt][jj] = 0.f;

    gemm_issue(As, Bs, Ap, Bp, 0, 0, lr2, lc4);
    gemm_issue(As, Bs, Ap, Bp, 1, 32, lr2, lc4);

    int cur = 0, nxt = 2;
    for (int it = 0; it < 32; it++) {
        if (it < 31) asm volatile("cp.async.wait_group 1;" ::: "memory");
        else         asm volatile("cp.async.wait_group 0;" ::: "memory");
        __syncthreads();
        if (it + 2 < 32) {
            gemm_issue(As, Bs, Ap, Bp, nxt, (it + 2) * 32, lr2, lc4);
            if (++nxt == 3) nxt = 0;
        }

        const uint32_t Ab = As_s + cur * (GPITCH * 4);
        const uint32_t Bb = Bs_s + cur * (GPITCH * 4);
        #pragma unroll
        for (int ks = 0; ks < 4; ks++) {
            uint32_t af[4][4];
            #pragma unroll
            for (int mt = 0; mt < 4; mt++) ldsm4(af[mt], Ab + a_off[mt] + ks * 32);
            uint32_t bf[8];
            #pragma unroll
            for (int p = 0; p < 2; p++) ldsm4(bf + 4 * p, Bb + b_off[p] + ks * 32);
            #pragma unroll
            for (int mt = 0; mt < 4; mt++)
                #pragma unroll
                for (int nt = 0; nt < 4; nt++)
                    mma_tf32(acc[mt][nt], af[mt], &bf[2 * nt]);
        }
        if (++cur == 3) cur = 0;
    }
}

__global__ __launch_bounds__(256) void gemm_qkv_mma(
    const float* __restrict__ sinp, const float* __restrict__ cosp)
{
    extern __shared__ uint32_t smu[];
    const int tid = threadIdx.x;
    const int m0 = blockIdx.y * 128, n0 = blockIdx.x * 128;
    float acc[4][4][4];
    mma_mainloop(g_x32 + (size_t)m0 * CDIM, g_wt_qkv + (size_t)n0 * CDIM, acc, tid, smu);

    const int lane = tid & 31, wid = tid >> 5;
    const int wm = wid >> 2, wn = wid & 3;
    const int sec = n0 >> 10;
    const int nb = n0 & 1023;

    #pragma unroll
    for (int mt = 0; mt < 4; mt++) {
        #pragma unroll
        for (int nt = 0; nt < 4; nt++) {
            const int col = wn * 32 + nt * 8 + (lane & 3) * 2;
            const int nc = nb + col;
            const int h = nc >> 6, d = nc & 63;
            #pragma unroll
            for (int half = 0; half < 2; half++) {
                const int row = m0 + wm * 64 + mt * 16 + (lane >> 2) + half * 8;
                const int b = row >> 11, t = row & 2047;
                const int bh = b * NH + h;
                float v0 = acc[mt][nt][half * 2], v1 = acc[mt][nt][half * 2 + 1];
                if (sec < 2) {
                    float ca = cosp[t * HD + d], sa = sinp[t * HD + d];
                    float o0 = v0 * ca - v1 * sa;
                    float o1 = v1 * ca + v0 * sa;
                    if (sec == 0) { o0 *= 0.125f; o1 *= 0.125f; }   // fold softmax scale (exact)
                    float* dst = (sec == 0) ? g_q : g_k;
                    *(float2*)(dst + (((size_t)bh * TDIM + t) * HD + d)) =
                        make_float2(__uint_as_float(cvt_tf32(o0)), __uint_as_float(cvt_tf32(o1)));
                } else {
                    g_vt[((size_t)bh * HD + d) * TDIM + t]     = __uint_as_float(cvt_tf32(v0));
                    g_vt[((size_t)bh * HD + d + 1) * TDIM + t] = __uint_as_float(cvt_tf32(v1));
                }
            }
        }
    }
}

__global__ __launch_bounds__(256) void gemm_proj_mma(float* __restrict__ out)
{
    extern __shared__ uint32_t smu[];
    const int tid = threadIdx.x;
    const int m0 = blockIdx.y * 128, n0 = blockIdx.x * 128;
    float acc[4][4][4];
    mma_mainloop(g_y + (size_t)m0 * CDIM, g_wt_proj + (size_t)n0 * CDIM, acc, tid, smu);

    const int lane = tid & 31, wid = tid >> 5;
    const int wm = wid >> 2, wn = wid & 3;
    #pragma unroll
    for (int mt = 0; mt < 4; mt++) {
        #pragma unroll
        for (int nt = 0; nt < 4; nt++) {
            const int col = n0 + wn * 32 + nt * 8 + (lane & 3) * 2;
            #pragma unroll
            for (int half = 0; half < 2; half++) {
                const int row = m0 + wm * 64 + mt * 16 + (lane >> 2) + half * 8;
                *(float2*)(out + (size_t)row * CDIM + col) =
                    make_float2(acc[mt][nt][half * 2], acc[mt][nt][half * 2 + 1]);
            }
        }
    }
}

// ================= flash attention: 128 q-rows/CTA, 8 warps, full-ldmatrix =================
// K/V tiles (64 k) fetched ONCE per 128 q-rows (was twice). Per-warp compute unchanged.
// smem floats: Qs[128][68] @0, Ps[128][68] @8704, Ks[2][64][68] @17408, Vt[2][64][68] @26112
#define FA_SMEM 139264

__global__ __launch_bounds__(256) void flash_mma()
{
    extern __shared__ float sm[];
    float* Qs = sm;                  // [128][68]
    float* Ps = sm + 8704;           // [128][68]
    float* KsB = sm + 17408;         // [2][64][68]
    float* VsB = sm + 26112;         // [2][64][68]  (Vt: rows=d, cols=t)

    const int bh = blockIdx.x;
    const int qt = 15 - blockIdx.y;          // long CTAs first
    const int q0 = qt * 128;
    const int ktmax = 2 * qt + 1;
    const int tid = threadIdx.x;
    const int lane = tid & 31, wid = tid >> 5;
    const int fr = lane >> 2, fc = lane & 3;
    const int lq = lane & 7, j = lane >> 3;
    const int wq = wid * 16;                 // 0..112

    const float* qb = g_q + (size_t)bh * TDIM * HD;
    const float* kb = g_k + (size_t)bh * TDIM * HD;
    const float* vtb = g_vt + (size_t)bh * HD * TDIM;

    const uint32_t Qs_s = (uint32_t)__cvta_generic_to_shared(Qs);
    const uint32_t Ps_s = (uint32_t)__cvta_generic_to_shared(Ps);
    const uint32_t Ks_s = (uint32_t)__cvta_generic_to_shared(KsB);
    const uint32_t Vs_s = (uint32_t)__cvta_generic_to_shared(VsB);

    const uint32_t q_off = ((wq + (j & 1) * 8 + lq) * 68 + (j >> 1) * 4) * 4;
    uint32_t b_off[4];
    #pragma unroll
    for (int p = 0; p < 4; p++)
        b_off[p] = (((2 * p + (j >> 1)) * 8 + lq) * 68 + (j & 1) * 4) * 4;

    // Q tile: 128 rows x 16 float4, 256 threads -> 8 iters
    #pragma unroll
    for (int i = 0; i < 8; i++) {
        int lin = tid + i * 256;
        int r = lin >> 4, c4 = (lin & 15) * 4;
        *(float4*)(Qs + r * 68 + c4) = *(const float4*)(qb + (size_t)(q0 + r) * HD + c4);
    }
    // K/V tile 0: 64 rows x 16 float4 -> 4 iters
    #pragma unroll
    for (int i = 0; i < 4; i++) {
        int lin = tid + i * 256;
        int r = lin >> 4, c4 = (lin & 15) * 4;
        cp16((uint32_t)__cvta_generic_to_shared(KsB + r * 68 + c4),
             kb + (size_t)r * HD + c4);
        cp16((uint32_t)__cvta_generic_to_shared(VsB + r * 68 + c4),
             vtb + (size_t)r * TDIM + c4);
    }
    asm volatile("cp.async.commit_group;" ::: "memory");

    float o[8][4];
    #pragma unroll
    for (int nt = 0; nt < 8; nt++)
        #pragma unroll
        for (int jj = 0; jj < 4; jj++) o[nt][jj] = 0.f;
    float m0 = -1e30f, m1 = -1e30f, l0 = 0.f, l1 = 0.f;

    for (int kt = 0; kt <= ktmax; kt++) {
        const int buf = kt & 1;
        if (kt < ktmax) {
            const int kr = (kt + 1) * 64;
            float* Kn = KsB + (buf ^ 1) * 4352;
            float* Vn = VsB + (buf ^ 1) * 4352;
            #pragma unroll
            for (int i = 0; i < 4; i++) {
                int lin = tid + i * 256;
                int r = lin >> 4, c4 = (lin & 15) * 4;
                cp16((uint32_t)__cvta_generic_to_shared(Kn + r * 68 + c4),
                     kb + (size_t)(kr + r) * HD + c4);
                cp16((uint32_t)__cvta_generic_to_shared(Vn + r * 68 + c4),
                     vtb + (size_t)r * TDIM + kr + c4);
            }
            asm volatile("cp.async.commit_group;" ::: "memory");
            asm volatile("cp.async.wait_group 1;" ::: "memory");
        } else {
            asm volatile("cp.async.wait_group 0;" ::: "memory");
        }
        __syncthreads();

        const uint32_t Kb_s = Ks_s + buf * (4352 * 4);
        const uint32_t Vb_s = Vs_s + buf * (4352 * 4);

        // ---- S = Q K^T  (scale pre-folded into Q) ----
        float s[8][4];
        #pragma unroll
        for (int nt = 0; nt < 8; nt++)
            #pragma unroll
            for (int jj = 0; jj < 4; jj++) s[nt][jj] = 0.f;
        #pragma unroll
        for (int ks = 0; ks < 8; ks++) {
            uint32_t a[4];
            ldsm4(a, Qs_s + q_off + ks * 32);
            uint32_t kf[16];
            #pragma unroll
            for (int p = 0; p < 4; p++) ldsm4(kf + 4 * p, Kb_s + b_off[p] + ks * 32);
            #pragma unroll
            for (int nt = 0; nt < 8; nt++)
                mma_tf32(s[nt], a, &kf[2 * nt]);
        }

        // causal mask (warp-uniform branch; element test in global coords)
        if ((kt + 1) * 64 > q0 + wq) {
            const int r0 = q0 + wq + fr, r1 = r0 + 8;
            #pragma unroll
            for (int nt = 0; nt < 8; nt++) {
                const int cl = kt * 64 + nt * 8 + 2 * fc;
                if (cl > r0)     s[nt][0] = -1e30f;
                if (cl + 1 > r0) s[nt][1] = -1e30f;
                if (cl > r1)     s[nt][2] = -1e30f;
                if (cl + 1 > r1) s[nt][3] = -1e30f;
            }
        }

        // ---- online softmax (warp-local quad shuffles) ----
        float mx0 = -1e30f, mx1 = -1e30f;
        #pragma unroll
        for (int nt = 0; nt < 8; nt++) {
            mx0 = fmaxf(mx0, fmaxf(s[nt][0], s[nt][1]));
            mx1 = fmaxf(mx1, fmaxf(s[nt][2], s[nt][3]));
        }
        mx0 = fmaxf(mx0, __shfl_xor_sync(0xffffffffu, mx0, 1));
        mx0 = fmaxf(mx0, __shfl_xor_sync(0xffffffffu, mx0, 2));
        mx1 = fmaxf(mx1, __shfl_xor_sync(0xffffffffu, mx1, 1));
        mx1 = fmaxf(mx1, __shfl_xor_sync(0xffffffffu, mx1, 2));
        const float mn0 = fmaxf(m0, mx0), mn1 = fmaxf(m1, mx1);
        const float al0 = __expf(m0 - mn0), al1 = __expf(m1 - mn1);
        m0 = mn0; m1 = mn1;

        float ps0 = 0.f, ps1 = 0.f;
        #pragma unroll
        for (int nt = 0; nt < 8; nt++) {
            float p0 = __expf(s[nt][0] - mn0);
            float p1 = __expf(s[nt][1] - mn0);
            float p2 = __expf(s[nt][2] - mn1);
            float p3 = __expf(s[nt][3] - mn1);
            ps0 += p0 + p1; ps1 += p2 + p3;
            const int cl = nt * 8 + 2 * fc;
            Ps[(wq + fr) * 68 + cl]     = p0;
            Ps[(wq + fr) * 68 + cl + 1] = p1;
            Ps[(wq + fr + 8) * 68 + cl]     = p2;
            Ps[(wq + fr + 8) * 68 + cl + 1] = p3;
        }
        ps0 += __shfl_xor_sync(0xffffffffu, ps0, 1);
        ps0 += __shfl_xor_sync(0xffffffffu, ps0, 2);
        ps1 += __shfl_xor_sync(0xffffffffu, ps1, 1);
        ps1 += __shfl_xor_sync(0xffffffffu, ps1, 2);
        l0 = l0 * al0 + ps0;
        l1 = l1 * al1 + ps1;
        #pragma unroll
        for (int nt = 0; nt < 8; nt++) {
            o[nt][0] *= al0; o[nt][1] *= al0;
            o[nt][2] *= al1; o[nt][3] *= al1;
        }
        __syncwarp();

        // ---- O += P V  (ldmatrix on Vt) ----
        #pragma unroll
        for (int ks = 0; ks < 8; ks++) {
            uint32_t a[4];
            ldsm4(a, Ps_s + q_off + ks * 32);
            uint32_t vf[16];
            #pragma unroll
            for (int p = 0; p < 4; p++) ldsm4(vf + 4 * p, Vb_s + b_off[p] + ks * 32);
            #pragma unroll
            for (int nt = 0; nt < 8; nt++)
                mma_tf32(o[nt], a, &vf[2 * nt]);
        }
        __syncthreads();
    }

    // ---- epilogue: O/l -> g_y [B,T,C], tf32-rounded ----
    const float inv0 = 1.0f / l0, inv1 = 1.0f / l1;
    const int b = bh >> 4, h = bh & 15;
    const int t0 = q0 + wq + fr, t1 = t0 + 8;
    #pragma unroll
    for (int nt = 0; nt < 8; nt++) {
        const int d = nt * 8 + 2 * fc;
        *(float2*)(g_y + (size_t)(b * TDIM + t0) * CDIM + h * HD + d) =
            make_float2(__uint_as_float(cvt_tf32(o[nt][0] * inv0)),
                        __uint_as_float(cvt_tf32(o[nt][1] * inv0)));
        *(float2*)(g_y + (size_t)(b * TDIM + t1) * CDIM + h * HD + d) =
            make_float2(__uint_as_float(cvt_tf32(o[nt][2] * inv1)),
                        __uint_as_float(cvt_tf32(o[nt][3] * inv1)));
    }
}

// ================= launch =================
extern "C" void kernel_launch(void* const* d_in, const int* in_sizes, int n_in,
                              void* d_out, int out_size)
{
    const float* x     = (const float*)d_in[0];
    const float* sinp  = (const float*)d_in[1];
    const float* cosp  = (const float*)d_in[2];
    const float* Wqkv  = (const float*)d_in[3];
    const float* Wproj = (const float*)d_in[4];
    float* out = (float*)d_out;

    float* wt_qkv;  cudaGetSymbolAddress((void**)&wt_qkv,  g_wt_qkv);
    float* wt_proj; cudaGetSymbolAddress((void**)&wt_proj, g_wt_proj);

    cudaFuncSetAttribute(flash_mma,     cudaFuncAttributeMaxDynamicSharedMemorySize, FA_SMEM);
    cudaFuncSetAttribute(gemm_qkv_mma,  cudaFuncAttributeMaxDynamicSharedMemorySize, GSMEM);
    cudaFuncSetAttribute(gemm_proj_mma, cudaFuncAttributeMaxDynamicSharedMemorySize, GSMEM);

    cvt_x32_kernel<<<MDIM * CDIM / 4 / 256, 256>>>(x);
    transpose_cvt<<<dim3(NQKV / 32, CDIM / 32), 256>>>(Wqkv,  wt_qkv,  NQKV);
    transpose_cvt<<<dim3(CDIM / 32, CDIM / 32), 256>>>(Wproj, wt_proj, CDIM);

    gemm_qkv_mma<<<dim3(NQKV / 128, MDIM / 128), 256, GSMEM>>>(sinp, cosp);
    flash_mma<<<dim3(BDIM * NH, TDIM / 128), 256, FA_SMEM>>>();
    gemm_proj_mma<<<dim3(CDIM / 128, MDIM / 128), 256, GSMEM>>>(out);
}